// round 12
// baseline (speedup 1.0000x reference)
#include <cuda_runtime.h>
#include <cuda_fp16.h>
#include <math.h>
#include <stdint.h>

#define B_ 32
#define T_ 2048
#define D_ 512
#define U_ 512
#define MT 65536            // B_*T_

// ---- score GEMM tiling ----
#define TILE_M 128
#define TILE_N 128
#define KC 64               // K elems per pipeline chunk (128B fp16 rows, SW128)
#define NCHUNK 8            // 512/64
#define NSTAGE 3
#define A_H 0               // A plane: 128 rows x 128B = 16KB
#define B_H 16384           // B plane: 16KB
#define STAGE 32768
#define SMEM_TOTAL (NSTAGE*STAGE + 1024)   // 99328 B -> 2 CTAs/SM

// ---- scratch (device globals: allocation-free) ----
__device__ float g_score[MT];
__device__ float g_pq[B_ * U_];
__device__ __half g_vh[(size_t)MT * D_];
__device__ __half g_w1h[U_ * D_];   // [n][k] transposed, K-major

// ---------------------------------------------------------------------------
// PTX helpers — baseline (non-"a") features only
// ---------------------------------------------------------------------------
__device__ __forceinline__ uint32_t smem_u32(const void* p) {
    uint32_t a;
    asm("{ .reg .u64 t; cvta.to.shared.u64 t, %1; cvt.u32.u64 %0, t; }" : "=r"(a) : "l"(p));
    return a;
}
#define SWZ(o) ((o) ^ (((o) >> 3) & 0x70))   // SW128 for 128B rows

__device__ __forceinline__ void cp16(uint32_t dst, const void* src) {
    asm volatile("cp.async.cg.shared.global [%0], [%1], 16;" :: "r"(dst), "l"(src));
}
__device__ __forceinline__ void ldm4(uint32_t* r, uint32_t addr) {
    asm volatile("ldmatrix.sync.aligned.m8n8.x4.shared.b16 {%0,%1,%2,%3}, [%4];"
                 : "=r"(r[0]), "=r"(r[1]), "=r"(r[2]), "=r"(r[3]) : "r"(addr));
}
__device__ __forceinline__ void mma_f16(float* d, const uint32_t* a,
                                        uint32_t b0, uint32_t b1) {
    asm volatile(
        "mma.sync.aligned.m16n8k16.row.col.f32.f16.f16.f32 "
        "{%0,%1,%2,%3}, {%4,%5,%6,%7}, {%8,%9}, {%0,%1,%2,%3};"
        : "+f"(d[0]), "+f"(d[1]), "+f"(d[2]), "+f"(d[3])
        : "r"(a[0]), "r"(a[1]), "r"(a[2]), "r"(a[3]), "r"(b0), "r"(b1));
}
__device__ __forceinline__ float tanh_fast(float x) {
    float y;
    asm("tanh.approx.f32 %0, %1;" : "=f"(y) : "f"(x));
    return y;
}

// ---------------------------------------------------------------------------
// values fp32 -> fp16
// ---------------------------------------------------------------------------
__global__ void convert_values_kernel(const float* __restrict__ v) {
    const float4* v4 = (const float4*)v;
    __half2* vh2 = (__half2*)g_vh;
    size_t n4 = (size_t)MT * D_ / 4;
    for (size_t i = (size_t)blockIdx.x * blockDim.x + threadIdx.x; i < n4;
         i += (size_t)gridDim.x * blockDim.x) {
        float4 x = v4[i];
        __half2 h0, h1;
        h0.x = __float2half(x.x); h0.y = __float2half(x.y);
        h1.x = __float2half(x.z); h1.y = __float2half(x.w);
        vh2[2*i] = h0; vh2[2*i+1] = h1;
    }
}

// W1 [K][N] -> transposed fp16 [N][K]
__global__ void convert_w1_kernel(const float* __restrict__ W1) {
    __shared__ float t[32][33];
    int k0 = blockIdx.y * 32, n0 = blockIdx.x * 32;
    int tx = threadIdx.x & 31, ty = threadIdx.x >> 5;
    for (int r = ty; r < 32; r += 8) t[r][tx] = W1[(k0 + r) * U_ + n0 + tx];
    __syncthreads();
    for (int r = ty; r < 32; r += 8)
        g_w1h[(size_t)(n0 + r) * D_ + k0 + tx] = __float2half(t[tx][r]);
}

// ---------------------------------------------------------------------------
// proj_q + bias fold; also zeroes g_score (atomicAdd target)
// ---------------------------------------------------------------------------
__global__ void pq_kernel(const float* __restrict__ query,
                          const float* __restrict__ W2,
                          const float* __restrict__ W1b,
                          const float* __restrict__ W2b) {
    __shared__ float qs[D_];
    int b = blockIdx.x, u = threadIdx.x;
    qs[u] = query[b * D_ + u];
    for (int i = b * 512 + u; i < MT; i += B_ * 512) g_score[i] = 0.f;
    __syncthreads();
    float acc = 0.f;
#pragma unroll 8
    for (int d = 0; d < D_; d++) acc = fmaf(qs[d], W2[d * U_ + u], acc);
    g_pq[b * U_ + u] = acc + W1b[u] + W2b[u];
}

// ---------------------------------------------------------------------------
// Score GEMM: single fp16 mma.sync, 3-stage cp.async pipeline,
// fused tanh.approx/Vw epilogue. grid 2048 = 512 m-tiles x 4 n-slices.
// ---------------------------------------------------------------------------
extern __shared__ char smem_raw[];

__global__ __launch_bounds__(256, 2)
void score_kernel(const float* __restrict__ Vw) {
    const int tid  = threadIdx.x;
    const int lane = tid & 31;
    const int mtile = blockIdx.x >> 2;
    const int nq    = blockIdx.x & 3;
    const int row0  = mtile * TILE_M;
    const int b     = row0 >> 11;          // T_=2048
    const int n0    = nq * TILE_N;
    const int wid   = tid >> 5;
    const int m_w   = (wid >> 2) * 64;
    const int n_w   = (wid & 3) * 32;

    uint32_t sb = smem_u32(smem_raw);
    float* pqs = (float*)(smem_raw + NSTAGE * STAGE);
    float* vws = pqs + 128;
    if (tid < 128) {
        pqs[tid] = g_pq[b * U_ + n0 + tid];
        vws[tid] = Vw[n0 + tid];
    }

    // ldmatrix per-lane address components (XOR swizzle folded per-lane)
    const int rowA = lane & 15;
    const int colA = (lane >> 4) * 16;
    const uint32_t axor = (rowA & 7) * 16;
    const int rowB = (lane & 7) + ((lane >> 3) & 1) * 8;
    const int colB = (lane >> 4) * 16;
    const uint32_t bxor = (rowB & 7) * 16;

    float acc[4][4][4];
#pragma unroll
    for (int i = 0; i < 4; i++)
#pragma unroll
        for (int j = 0; j < 4; j++)
#pragma unroll
            for (int r = 0; r < 4; r++) acc[i][j][r] = 0.f;

    const __half* Agh = g_vh  + (size_t)row0 * D_;
    const __half* Bgh = g_w1h + (size_t)n0   * D_;

    // loader: each plane 1024 granules (16B); 256 thr x 4 per plane
    const int lrow = tid >> 1;
    const int lch0 = (tid & 1) * 4;

#define LOAD_CHUNK(c, s)                                                     \
    do {                                                                     \
        uint32_t st = sb + (s) * STAGE;                                      \
        int k0 = (c) * KC;                                                   \
        _Pragma("unroll")                                                    \
        for (int i = 0; i < 4; i++) {                                        \
            int c16 = lch0 + i;                                              \
            uint32_t doff = SWZ(lrow * 128 + c16 * 16);                      \
            size_t soff = (size_t)lrow * D_ + k0 + c16 * 8;                  \
            cp16(st + A_H + doff, Agh + soff);                               \
            cp16(st + B_H + doff, Bgh + soff);                               \
        }                                                                    \
        asm volatile("cp.async.commit_group;" ::: "memory");                 \
    } while (0)

    // prologue: stages 0,1
    LOAD_CHUNK(0, 0);
    LOAD_CHUNK(1, 1);

    const uint32_t aho = A_H + (m_w + rowA) * 128;
    const uint32_t bho = B_H + (n_w + rowB) * 128;

    for (int c = 0; c < NCHUNK; c++) {
        if (c + 1 < NCHUNK)
            asm volatile("cp.async.wait_group 1;" ::: "memory");
        else
            asm volatile("cp.async.wait_group 0;" ::: "memory");
        __syncthreads();                    // also guards stage (c+2)%3 reuse

        if (c + 2 < NCHUNK) LOAD_CHUNK(c + 2, (c + 2) % NSTAGE);

        const uint32_t st = sb + (c % NSTAGE) * STAGE;
#pragma unroll
        for (int k = 0; k < 4; k++) {                 // 4 x k16 per 64-chunk
            const uint32_t ka = (uint32_t)((k * 32 + colA) ^ axor);
            const uint32_t kb = (uint32_t)((k * 32 + colB) ^ bxor);

            uint32_t ah[4][4], bh[2][4];
#pragma unroll
            for (int i = 0; i < 4; i++)
                ldm4(ah[i], st + aho + i * 2048 + ka);
#pragma unroll
            for (int jj = 0; jj < 2; jj++)
                ldm4(bh[jj], st + bho + jj * 2048 + kb);
#pragma unroll
            for (int i = 0; i < 4; i++)
#pragma unroll
                for (int j = 0; j < 4; j++)
                    mma_f16(acc[i][j], ah[i],
                            bh[j >> 1][j & 1], bh[j >> 1][2 + (j & 1)]);
        }
    }

    // Epilogue: tanh.approx(acc+pq)*Vw, reduce over n (shfl -> atomicAdd)
    float part[4][2];
#pragma unroll
    for (int i = 0; i < 4; i++) { part[i][0] = 0.f; part[i][1] = 0.f; }
#pragma unroll
    for (int i = 0; i < 4; i++)
#pragma unroll
        for (int j = 0; j < 4; j++)
#pragma unroll
            for (int r = 0; r < 4; r++) {
                int nl = n_w + j * 8 + 2 * (lane & 3) + (r & 1);
                float x = acc[i][j][r] + pqs[nl];
                part[i][r >> 1] += tanh_fast(x) * vws[nl];
            }
#pragma unroll
    for (int i = 0; i < 4; i++)
#pragma unroll
        for (int h = 0; h < 2; h++) {
            float v = part[i][h];
            v += __shfl_xor_sync(0xffffffffu, v, 1);
            v += __shfl_xor_sync(0xffffffffu, v, 2);
            if ((lane & 3) == 0)
                atomicAdd(&g_score[row0 + m_w + i * 16 + h * 8 + (lane >> 2)], v);
        }
}

// ---------------------------------------------------------------------------
// Softmax over T per batch; weights -> d_out[B*D ..)
// ---------------------------------------------------------------------------
__global__ void softmax_kernel(float* __restrict__ out) {
    __shared__ float sm[256];
    int b = blockIdx.x, tid = threadIdx.x;
    const float* sc = g_score + b * T_;
    float m = -1e30f;
    for (int t = tid; t < T_; t += 256) m = fmaxf(m, sc[t]);
    sm[tid] = m; __syncthreads();
    for (int s = 128; s > 0; s >>= 1) {
        if (tid < s) sm[tid] = fmaxf(sm[tid], sm[tid + s]);
        __syncthreads();
    }
    float mx = sm[0]; __syncthreads();
    float sum = 0.f;
    for (int t = tid; t < T_; t += 256) sum += __expf(sc[t] - mx);
    sm[tid] = sum; __syncthreads();
    for (int s = 128; s > 0; s >>= 1) {
        if (tid < s) sm[tid] += sm[tid + s];
        __syncthreads();
    }
    float inv = 1.f / sm[0];
    float* w = out + B_ * D_ + b * T_;
    for (int t = tid; t < T_; t += 256) w[t] = __expf(sc[t] - mx) * inv;
}

// ---------------------------------------------------------------------------
// context[b,d] = sum_t w[b,t] * vh[b,t,d]  (fp16 values, L2-hot from score)
// grid (8, 32), 256 threads: 64 d-groups (8 halves each) x 4-way t-interleave
// ---------------------------------------------------------------------------
__global__ void context_kernel(float* __restrict__ out) {
    int b  = blockIdx.y;
    int t0 = blockIdx.x * 256;
    int dg = (threadIdx.x & 63) * 8;
    int th = threadIdx.x >> 6;
    const float* w = out + B_ * D_ + b * T_ + t0;
    const uint4* v = (const uint4*)(g_vh + ((size_t)b * T_ + t0) * D_ + dg);
    float acc[8];
#pragma unroll
    for (int j = 0; j < 8; j++) acc[j] = 0.f;
#pragma unroll 4
    for (int t = th; t < 256; t += 4) {
        float wt = w[t];
        uint4 x = v[(size_t)t * (D_ / 8)];
        const __half2* h2 = (const __half2*)&x;
#pragma unroll
        for (int j = 0; j < 4; j++) {
            float2 f = __half22float2(h2[j]);
            acc[2*j]     = fmaf(wt, f.x, acc[2*j]);
            acc[2*j + 1] = fmaf(wt, f.y, acc[2*j + 1]);
        }
    }
    float* o = out + b * D_ + dg;
#pragma unroll
    for (int j = 0; j < 8; j++) atomicAdd(o + j, acc[j]);
}

// ---------------------------------------------------------------------------
extern "C" void kernel_launch(void* const* d_in, const int* in_sizes, int n_in,
                              void* d_out, int out_size) {
    const float* values = (const float*)d_in[0];
    const float* query  = (const float*)d_in[1];
    const float* W1w    = (const float*)d_in[2];
    const float* W1b    = (const float*)d_in[3];
    const float* W2w    = (const float*)d_in[4];
    const float* W2b    = (const float*)d_in[5];
    const float* Vw     = (const float*)d_in[6];
    // d_in[7] (V_b) unused: softmax is shift-invariant.
    float* out = (float*)d_out;

    cudaFuncSetAttribute(score_kernel, cudaFuncAttributeMaxDynamicSharedMemorySize,
                         SMEM_TOTAL);

    cudaMemsetAsync(out, 0, (size_t)B_ * D_ * sizeof(float), 0);
    convert_values_kernel<<<8192, 256>>>(values);
    convert_w1_kernel<<<dim3(16, 16), 256>>>(W1w);
    pq_kernel<<<B_, 512>>>(query, W2w, W1b, W2b);
    score_kernel<<<2048, 256, SMEM_TOTAL>>>(Vw);
    softmax_kernel<<<B_, 256>>>(out);
    context_kernel<<<dim3(8, B_), 256>>>(out);
}

// round 13
// speedup vs baseline: 1.0151x; 1.0151x over previous
#include <cuda_runtime.h>
#include <cuda_fp16.h>
#include <math.h>
#include <stdint.h>

#define B_ 32
#define T_ 2048
#define D_ 512
#define U_ 512
#define MT 65536            // B_*T_

// ---- score GEMM tiling ----
#define TILE_M 128
#define TILE_N 128
#define KC 64               // K elems per pipeline chunk (128B fp16 rows, SW128)
#define NCHUNK 8            // 512/64
#define A_H 0               // A plane: 128 rows x 128B = 16KB
#define B_H 16384           // B plane: 16KB
#define STAGE 32768
#define SMEM_TOTAL (2*STAGE + 1024)   // 66560 B -> 2 CTAs/SM

// ---- scratch (device globals: allocation-free) ----
__device__ float g_score[MT];
__device__ float g_pq[B_ * U_];
__device__ __half g_vh[(size_t)MT * D_];
__device__ __half g_w1h[U_ * D_];   // [n][k] transposed, K-major

// ---------------------------------------------------------------------------
// PTX helpers — baseline (non-"a") features only
// ---------------------------------------------------------------------------
__device__ __forceinline__ uint32_t smem_u32(const void* p) {
    uint32_t a;
    asm("{ .reg .u64 t; cvta.to.shared.u64 t, %1; cvt.u32.u64 %0, t; }" : "=r"(a) : "l"(p));
    return a;
}
#define SWZ(o) ((o) ^ (((o) >> 3) & 0x70))   // SW128 for 128B rows

__device__ __forceinline__ void cp16(uint32_t dst, const void* src) {
    asm volatile("cp.async.cg.shared.global [%0], [%1], 16;" :: "r"(dst), "l"(src));
}
__device__ __forceinline__ void ldm4(uint32_t* r, uint32_t addr) {
    asm volatile("ldmatrix.sync.aligned.m8n8.x4.shared.b16 {%0,%1,%2,%3}, [%4];"
                 : "=r"(r[0]), "=r"(r[1]), "=r"(r[2]), "=r"(r[3]) : "r"(addr));
}
__device__ __forceinline__ void mma_f16(float* d, const uint32_t* a,
                                        uint32_t b0, uint32_t b1) {
    asm volatile(
        "mma.sync.aligned.m16n8k16.row.col.f32.f16.f16.f32 "
        "{%0,%1,%2,%3}, {%4,%5,%6,%7}, {%8,%9}, {%0,%1,%2,%3};"
        : "+f"(d[0]), "+f"(d[1]), "+f"(d[2]), "+f"(d[3])
        : "r"(a[0]), "r"(a[1]), "r"(a[2]), "r"(a[3]), "r"(b0), "r"(b1));
}
__device__ __forceinline__ float tanh_fast(float x) {
    float y;
    asm("tanh.approx.f32 %0, %1;" : "=f"(y) : "f"(x));
    return y;
}

// ---------------------------------------------------------------------------
// values fp32 -> fp16
// ---------------------------------------------------------------------------
__global__ void convert_values_kernel(const float* __restrict__ v) {
    const float4* v4 = (const float4*)v;
    __half2* vh2 = (__half2*)g_vh;
    size_t n4 = (size_t)MT * D_ / 4;
    for (size_t i = (size_t)blockIdx.x * blockDim.x + threadIdx.x; i < n4;
         i += (size_t)gridDim.x * blockDim.x) {
        float4 x = v4[i];
        __half2 h0, h1;
        h0.x = __float2half(x.x); h0.y = __float2half(x.y);
        h1.x = __float2half(x.z); h1.y = __float2half(x.w);
        vh2[2*i] = h0; vh2[2*i+1] = h1;
    }
}

// W1 [K][N] -> transposed fp16 [N][K]
__global__ void convert_w1_kernel(const float* __restrict__ W1) {
    __shared__ float t[32][33];
    int k0 = blockIdx.y * 32, n0 = blockIdx.x * 32;
    int tx = threadIdx.x & 31, ty = threadIdx.x >> 5;
    for (int r = ty; r < 32; r += 8) t[r][tx] = W1[(k0 + r) * U_ + n0 + tx];
    __syncthreads();
    for (int r = ty; r < 32; r += 8)
        g_w1h[(size_t)(n0 + r) * D_ + k0 + tx] = __float2half(t[tx][r]);
}

// ---------------------------------------------------------------------------
// proj_q + bias fold; also zeroes g_score (atomicAdd target)
// ---------------------------------------------------------------------------
__global__ void pq_kernel(const float* __restrict__ query,
                          const float* __restrict__ W2,
                          const float* __restrict__ W1b,
                          const float* __restrict__ W2b) {
    __shared__ float qs[D_];
    int b = blockIdx.x, u = threadIdx.x;
    qs[u] = query[b * D_ + u];
    for (int i = b * 512 + u; i < MT; i += B_ * 512) g_score[i] = 0.f;
    __syncthreads();
    float acc = 0.f;
#pragma unroll 8
    for (int d = 0; d < D_; d++) acc = fmaf(qs[d], W2[d * U_ + u], acc);
    g_pq[b * U_ + u] = acc + W1b[u] + W2b[u];
}

// ---------------------------------------------------------------------------
// Score GEMM: single fp16 mma.sync, 2-stage cp.async pipeline (R10 structure),
// fused tanh.approx/Vw epilogue. grid 2048 = 512 m-tiles x 4 n-slices.
// ---------------------------------------------------------------------------
extern __shared__ char smem_raw[];

__global__ __launch_bounds__(256, 2)
void score_kernel(const float* __restrict__ Vw) {
    const int tid  = threadIdx.x;
    const int lane = tid & 31;
    const int mtile = blockIdx.x >> 2;
    const int nq    = blockIdx.x & 3;
    const int row0  = mtile * TILE_M;
    const int b     = row0 >> 11;          // T_=2048
    const int n0    = nq * TILE_N;
    const int wid   = tid >> 5;
    const int m_w   = (wid >> 2) * 64;
    const int n_w   = (wid & 3) * 32;

    uint32_t sb = smem_u32(smem_raw);
    float* pqs = (float*)(smem_raw + 2 * STAGE);
    float* vws = pqs + 128;
    if (tid < 128) {
        pqs[tid] = g_pq[b * U_ + n0 + tid];
        vws[tid] = Vw[n0 + tid];
    }

    // ldmatrix per-lane address components (XOR swizzle folded per-lane)
    const int rowA = lane & 15;
    const int colA = (lane >> 4) * 16;                   // 16B chunk within k16 step
    const uint32_t axor = (rowA & 7) * 16;
    const int rowB = (lane & 7) + ((lane >> 3) & 1) * 8;
    const int colB = (lane >> 4) * 16;
    const uint32_t bxor = (rowB & 7) * 16;

    float acc[4][4][4];
#pragma unroll
    for (int i = 0; i < 4; i++)
#pragma unroll
        for (int j = 0; j < 4; j++)
#pragma unroll
            for (int r = 0; r < 4; r++) acc[i][j][r] = 0.f;

    const __half* Agh = g_vh  + (size_t)row0 * D_;
    const __half* Bgh = g_w1h + (size_t)n0   * D_;

    // loader: each plane 1024 granules (16B); 256 thr x 4 iters per plane
    const int lrow = tid >> 1;
    const int lch0 = (tid & 1) * 4;

#define LOAD_CHUNK(c, s)                                                     \
    do {                                                                     \
        uint32_t st = sb + (s) * STAGE;                                      \
        int k0 = (c) * KC;                                                   \
        _Pragma("unroll")                                                    \
        for (int i = 0; i < 4; i++) {                                        \
            int c16 = lch0 + i;                                              \
            uint32_t doff = SWZ(lrow * 128 + c16 * 16);                      \
            size_t soff = (size_t)lrow * D_ + k0 + c16 * 8;                  \
            cp16(st + A_H + doff, Agh + soff);                               \
            cp16(st + B_H + doff, Bgh + soff);                               \
        }                                                                    \
        asm volatile("cp.async.commit_group;" ::: "memory");                 \
    } while (0)

    LOAD_CHUNK(0, 0);

    // per-lane fragment bases (row part linear; col part XORed per k-step)
    const uint32_t aho = A_H + (m_w + rowA) * 128;
    const uint32_t bho = B_H + (n_w + rowB) * 128;

    for (int c = 0; c < NCHUNK; c++) {
        int s = c & 1;
        if (c + 1 < NCHUNK) {
            LOAD_CHUNK(c + 1, s ^ 1);
            asm volatile("cp.async.wait_group 1;" ::: "memory");
        } else {
            asm volatile("cp.async.wait_group 0;" ::: "memory");
        }
        __syncthreads();

        const uint32_t st = sb + s * STAGE;
#pragma unroll
        for (int k = 0; k < 4; k++) {                 // 4 x k16 per 64-chunk
            const uint32_t ka = (uint32_t)((k * 32 + colA) ^ axor);
            const uint32_t kb = (uint32_t)((k * 32 + colB) ^ bxor);

            uint32_t ah[4][4], bh[2][4];
#pragma unroll
            for (int i = 0; i < 4; i++)
                ldm4(ah[i], st + aho + i * 2048 + ka);
#pragma unroll
            for (int jj = 0; jj < 2; jj++)
                ldm4(bh[jj], st + bho + jj * 2048 + kb);
#pragma unroll
            for (int i = 0; i < 4; i++)
#pragma unroll
                for (int j = 0; j < 4; j++)
                    mma_f16(acc[i][j], ah[i],
                            bh[j >> 1][j & 1], bh[j >> 1][2 + (j & 1)]);
        }
        __syncthreads();
    }

    // Epilogue: tanh.approx(acc+pq)*Vw, reduce over n (shfl -> atomicAdd)
    float part[4][2];
#pragma unroll
    for (int i = 0; i < 4; i++) { part[i][0] = 0.f; part[i][1] = 0.f; }
#pragma unroll
    for (int i = 0; i < 4; i++)
#pragma unroll
        for (int j = 0; j < 4; j++)
#pragma unroll
            for (int r = 0; r < 4; r++) {
                int nl = n_w + j * 8 + 2 * (lane & 3) + (r & 1);
                float x = acc[i][j][r] + pqs[nl];
                part[i][r >> 1] += tanh_fast(x) * vws[nl];
            }
#pragma unroll
    for (int i = 0; i < 4; i++)
#pragma unroll
        for (int h = 0; h < 2; h++) {
            float v = part[i][h];
            v += __shfl_xor_sync(0xffffffffu, v, 1);
            v += __shfl_xor_sync(0xffffffffu, v, 2);
            if ((lane & 3) == 0)
                atomicAdd(&g_score[row0 + m_w + i * 16 + h * 8 + (lane >> 2)], v);
        }
}

// ---------------------------------------------------------------------------
// Softmax over T per batch; weights -> d_out[B*D ..)
// ---------------------------------------------------------------------------
__global__ void softmax_kernel(float* __restrict__ out) {
    __shared__ float sm[256];
    int b = blockIdx.x, tid = threadIdx.x;
    const float* sc = g_score + b * T_;
    float m = -1e30f;
    for (int t = tid; t < T_; t += 256) m = fmaxf(m, sc[t]);
    sm[tid] = m; __syncthreads();
    for (int s = 128; s > 0; s >>= 1) {
        if (tid < s) sm[tid] = fmaxf(sm[tid], sm[tid + s]);
        __syncthreads();
    }
    float mx = sm[0]; __syncthreads();
    float sum = 0.f;
    for (int t = tid; t < T_; t += 256) sum += __expf(sc[t] - mx);
    sm[tid] = sum; __syncthreads();
    for (int s = 128; s > 0; s >>= 1) {
        if (tid < s) sm[tid] += sm[tid + s];
        __syncthreads();
    }
    float inv = 1.f / sm[0];
    float* w = out + B_ * D_ + b * T_;
    for (int t = tid; t < T_; t += 256) w[t] = __expf(sc[t] - mx) * inv;
}

// ---------------------------------------------------------------------------
// context[b,d] = sum_t w[b,t] * vh[b,t,d]  (fp16 values, L2-hot from score)
// grid (8, 32), 256 threads: 64 d-groups (8 halves each) x 4-way t-interleave
// ---------------------------------------------------------------------------
__global__ void context_kernel(float* __restrict__ out) {
    int b  = blockIdx.y;
    int t0 = blockIdx.x * 256;
    int dg = (threadIdx.x & 63) * 8;
    int th = threadIdx.x >> 6;
    const float* w = out + B_ * D_ + b * T_ + t0;
    const uint4* v = (const uint4*)(g_vh + ((size_t)b * T_ + t0) * D_ + dg);
    float acc[8];
#pragma unroll
    for (int j = 0; j < 8; j++) acc[j] = 0.f;
#pragma unroll 4
    for (int t = th; t < 256; t += 4) {
        float wt = w[t];
        uint4 x = v[(size_t)t * (D_ / 8)];
        const __half2* h2 = (const __half2*)&x;
#pragma unroll
        for (int j = 0; j < 4; j++) {
            float2 f = __half22float2(h2[j]);
            acc[2*j]     = fmaf(wt, f.x, acc[2*j]);
            acc[2*j + 1] = fmaf(wt, f.y, acc[2*j + 1]);
        }
    }
    float* o = out + b * D_ + dg;
#pragma unroll
    for (int j = 0; j < 8; j++) atomicAdd(o + j, acc[j]);
}

// ---------------------------------------------------------------------------
extern "C" void kernel_launch(void* const* d_in, const int* in_sizes, int n_in,
                              void* d_out, int out_size) {
    const float* values = (const float*)d_in[0];
    const float* query  = (const float*)d_in[1];
    const float* W1w    = (const float*)d_in[2];
    const float* W1b    = (const float*)d_in[3];
    const float* W2w    = (const float*)d_in[4];
    const float* W2b    = (const float*)d_in[5];
    const float* Vw     = (const float*)d_in[6];
    // d_in[7] (V_b) unused: softmax is shift-invariant.
    float* out = (float*)d_out;

    cudaFuncSetAttribute(score_kernel, cudaFuncAttributeMaxDynamicSharedMemorySize,
                         SMEM_TOTAL);

    cudaMemsetAsync(out, 0, (size_t)B_ * D_ * sizeof(float), 0);
    convert_values_kernel<<<8192, 256>>>(values);
    convert_w1_kernel<<<dim3(16, 16), 256>>>(W1w);
    pq_kernel<<<B_, 512>>>(query, W2w, W1b, W2b);
    score_kernel<<<2048, 256, SMEM_TOTAL>>>(Vw);
    softmax_kernel<<<B_, 256>>>(out);
    context_kernel<<<dim3(8, B_), 256>>>(out);
}

// round 14
// speedup vs baseline: 1.3438x; 1.3238x over previous
#include <cuda_runtime.h>
#include <cuda_fp16.h>
#include <math.h>
#include <stdint.h>

#define B_ 32
#define T_ 2048
#define D_ 512
#define U_ 512
#define MT 65536            // B_*T_

// ---- score GEMM tiling ----
#define TILE_M 128
#define TILE_N 128
#define KC 64               // K elems per pipeline chunk (128B fp16 rows, SW128)
#define NCHUNK 8            // 512/64
#define A_H 0               // A plane: 128 rows x 128B = 16KB
#define B_H 16384           // B plane: 16KB
#define STAGE 32768
#define SMEM_TOTAL (2*STAGE + 1024)   // 66560 B -> 2 CTAs/SM

// ---- scratch (device globals: allocation-free) ----
__device__ float g_score[MT];
__device__ float g_pq[B_ * U_];
__device__ __half g_vh[(size_t)MT * D_];
__device__ __half g_w1h[U_ * D_];   // [n][k] transposed, K-major

// ---------------------------------------------------------------------------
// PTX helpers — baseline (non-"a") features only
// ---------------------------------------------------------------------------
__device__ __forceinline__ uint32_t smem_u32(const void* p) {
    uint32_t a;
    asm("{ .reg .u64 t; cvta.to.shared.u64 t, %1; cvt.u32.u64 %0, t; }" : "=r"(a) : "l"(p));
    return a;
}
#define SWZ(o) ((o) ^ (((o) >> 3) & 0x70))   // SW128 for 128B rows

__device__ __forceinline__ void cp16(uint32_t dst, const void* src) {
    asm volatile("cp.async.cg.shared.global [%0], [%1], 16;" :: "r"(dst), "l"(src));
}
__device__ __forceinline__ void ldm4(uint32_t* r, uint32_t addr) {
    asm volatile("ldmatrix.sync.aligned.m8n8.x4.shared.b16 {%0,%1,%2,%3}, [%4];"
                 : "=r"(r[0]), "=r"(r[1]), "=r"(r[2]), "=r"(r[3]) : "r"(addr));
}
__device__ __forceinline__ void mma_f16(float* d, const uint32_t* a,
                                        uint32_t b0, uint32_t b1) {
    asm volatile(
        "mma.sync.aligned.m16n8k16.row.col.f32.f16.f16.f32 "
        "{%0,%1,%2,%3}, {%4,%5,%6,%7}, {%8,%9}, {%0,%1,%2,%3};"
        : "+f"(d[0]), "+f"(d[1]), "+f"(d[2]), "+f"(d[3])
        : "r"(a[0]), "r"(a[1]), "r"(a[2]), "r"(a[3]), "r"(b0), "r"(b1));
}

// ---------------------------------------------------------------------------
// values fp32 -> fp16
// ---------------------------------------------------------------------------
__global__ void convert_values_kernel(const float* __restrict__ v) {
    const float4* v4 = (const float4*)v;
    __half2* vh2 = (__half2*)g_vh;
    size_t n4 = (size_t)MT * D_ / 4;
    for (size_t i = (size_t)blockIdx.x * blockDim.x + threadIdx.x; i < n4;
         i += (size_t)gridDim.x * blockDim.x) {
        float4 x = v4[i];
        __half2 h0, h1;
        h0.x = __float2half(x.x); h0.y = __float2half(x.y);
        h1.x = __float2half(x.z); h1.y = __float2half(x.w);
        vh2[2*i] = h0; vh2[2*i+1] = h1;
    }
}

// W1 [K][N] -> transposed fp16 [N][K]
__global__ void convert_w1_kernel(const float* __restrict__ W1) {
    __shared__ float t[32][33];
    int k0 = blockIdx.y * 32, n0 = blockIdx.x * 32;
    int tx = threadIdx.x & 31, ty = threadIdx.x >> 5;
    for (int r = ty; r < 32; r += 8) t[r][tx] = W1[(k0 + r) * U_ + n0 + tx];
    __syncthreads();
    for (int r = ty; r < 32; r += 8)
        g_w1h[(size_t)(n0 + r) * D_ + k0 + tx] = __float2half(t[tx][r]);
}

// ---------------------------------------------------------------------------
// proj_q + bias fold; also zeroes g_score (atomicAdd target)
// ---------------------------------------------------------------------------
__global__ void pq_kernel(const float* __restrict__ query,
                          const float* __restrict__ W2,
                          const float* __restrict__ W1b,
                          const float* __restrict__ W2b) {
    __shared__ float qs[D_];
    int b = blockIdx.x, u = threadIdx.x;
    qs[u] = query[b * D_ + u];
    for (int i = b * 512 + u; i < MT; i += B_ * 512) g_score[i] = 0.f;
    __syncthreads();
    float acc = 0.f;
#pragma unroll 8
    for (int d = 0; d < D_; d++) acc = fmaf(qs[d], W2[d * U_ + u], acc);
    g_pq[b * U_ + u] = acc + W1b[u] + W2b[u];
}

// ---------------------------------------------------------------------------
// Score GEMM: single fp16 mma.sync, 2-stage cp.async pipeline,
// fused tanhf/Vw epilogue (EXACT R11 structure — proven 143.7us config).
// grid 2048 = 512 m-tiles x 4 n-slices; 256 threads (8 warps, 64x32 each)
// ---------------------------------------------------------------------------
extern __shared__ char smem_raw[];

__global__ __launch_bounds__(256, 2)
void score_kernel(const float* __restrict__ Vw) {
    const int tid  = threadIdx.x;
    const int lane = tid & 31;
    const int mtile = blockIdx.x >> 2;
    const int nq    = blockIdx.x & 3;
    const int row0  = mtile * TILE_M;
    const int b     = row0 >> 11;          // T_=2048
    const int n0    = nq * TILE_N;
    const int wid   = tid >> 5;
    const int m_w   = (wid >> 2) * 64;
    const int n_w   = (wid & 3) * 32;

    uint32_t sb = smem_u32(smem_raw);
    float* pqs = (float*)(smem_raw + 2 * STAGE);
    float* vws = pqs + 128;
    if (tid < 128) {
        pqs[tid] = g_pq[b * U_ + n0 + tid];
        vws[tid] = Vw[n0 + tid];
    }

    // ldmatrix per-lane address components (XOR swizzle folded per-lane)
    const int rowA = lane & 15;
    const int colA = (lane >> 4) * 16;                   // 16B chunk within k16 step
    const uint32_t axor = (rowA & 7) * 16;
    const int rowB = (lane & 7) + ((lane >> 3) & 1) * 8;
    const int colB = (lane >> 4) * 16;
    const uint32_t bxor = (rowB & 7) * 16;

    float acc[4][4][4];
#pragma unroll
    for (int i = 0; i < 4; i++)
#pragma unroll
        for (int j = 0; j < 4; j++)
#pragma unroll
            for (int r = 0; r < 4; r++) acc[i][j][r] = 0.f;

    const __half* Agh = g_vh  + (size_t)row0 * D_;
    const __half* Bgh = g_w1h + (size_t)n0   * D_;

    // loader: each plane 1024 granules (16B); 256 thr x 4 iters per plane
    const int lrow = tid >> 1;
    const int lch0 = (tid & 1) * 4;

#define LOAD_CHUNK(c, s)                                                     \
    do {                                                                     \
        uint32_t st = sb + (s) * STAGE;                                      \
        int k0 = (c) * KC;                                                   \
        _Pragma("unroll")                                                    \
        for (int i = 0; i < 4; i++) {                                        \
            int c16 = lch0 + i;                                              \
            uint32_t doff = SWZ(lrow * 128 + c16 * 16);                      \
            size_t soff = (size_t)lrow * D_ + k0 + c16 * 8;                  \
            cp16(st + A_H + doff, Agh + soff);                               \
            cp16(st + B_H + doff, Bgh + soff);                               \
        }                                                                    \
        asm volatile("cp.async.commit_group;" ::: "memory");                 \
    } while (0)

    LOAD_CHUNK(0, 0);

    // per-lane fragment bases (row part linear; col part XORed per k-step)
    const uint32_t aho = A_H + (m_w + rowA) * 128;
    const uint32_t bho = B_H + (n_w + rowB) * 128;

    for (int c = 0; c < NCHUNK; c++) {
        int s = c & 1;
        if (c + 1 < NCHUNK) {
            LOAD_CHUNK(c + 1, s ^ 1);
            asm volatile("cp.async.wait_group 1;" ::: "memory");
        } else {
            asm volatile("cp.async.wait_group 0;" ::: "memory");
        }
        __syncthreads();

        const uint32_t st = sb + s * STAGE;
#pragma unroll
        for (int k = 0; k < 4; k++) {                 // 4 x k16 per 64-chunk
            const uint32_t ka = (uint32_t)((k * 32 + colA) ^ axor);
            const uint32_t kb = (uint32_t)((k * 32 + colB) ^ bxor);

            uint32_t ah[4][4], bh[2][4];
#pragma unroll
            for (int i = 0; i < 4; i++)
                ldm4(ah[i], st + aho + i * 2048 + ka);
#pragma unroll
            for (int jj = 0; jj < 2; jj++)
                ldm4(bh[jj], st + bho + jj * 2048 + kb);
#pragma unroll
            for (int i = 0; i < 4; i++)
#pragma unroll
                for (int j = 0; j < 4; j++)
                    mma_f16(acc[i][j], ah[i],
                            bh[j >> 1][j & 1], bh[j >> 1][2 + (j & 1)]);
        }
        __syncthreads();
    }

    // Epilogue: tanhf(acc+pq)*Vw, reduce over n (shfl -> atomicAdd)
    float part[4][2];
#pragma unroll
    for (int i = 0; i < 4; i++) { part[i][0] = 0.f; part[i][1] = 0.f; }
#pragma unroll
    for (int i = 0; i < 4; i++)
#pragma unroll
        for (int j = 0; j < 4; j++)
#pragma unroll
            for (int r = 0; r < 4; r++) {
                int nl = n_w + j * 8 + 2 * (lane & 3) + (r & 1);
                float x = acc[i][j][r] + pqs[nl];
                part[i][r >> 1] += tanhf(x) * vws[nl];
            }
#pragma unroll
    for (int i = 0; i < 4; i++)
#pragma unroll
        for (int h = 0; h < 2; h++) {
            float v = part[i][h];
            v += __shfl_xor_sync(0xffffffffu, v, 1);
            v += __shfl_xor_sync(0xffffffffu, v, 2);
            if ((lane & 3) == 0)
                atomicAdd(&g_score[row0 + m_w + i * 16 + h * 8 + (lane >> 2)], v);
        }
}

// ---------------------------------------------------------------------------
// Softmax over T per batch; weights -> d_out[B*D ..)
// ---------------------------------------------------------------------------
__global__ void softmax_kernel(float* __restrict__ out) {
    __shared__ float sm[256];
    int b = blockIdx.x, tid = threadIdx.x;
    const float* sc = g_score + b * T_;
    float m = -1e30f;
    for (int t = tid; t < T_; t += 256) m = fmaxf(m, sc[t]);
    sm[tid] = m; __syncthreads();
    for (int s = 128; s > 0; s >>= 1) {
        if (tid < s) sm[tid] = fmaxf(sm[tid], sm[tid + s]);
        __syncthreads();
    }
    float mx = sm[0]; __syncthreads();
    float sum = 0.f;
    for (int t = tid; t < T_; t += 256) sum += __expf(sc[t] - mx);
    sm[tid] = sum; __syncthreads();
    for (int s = 128; s > 0; s >>= 1) {
        if (tid < s) sm[tid] += sm[tid + s];
        __syncthreads();
    }
    float inv = 1.f / sm[0];
    float* w = out + B_ * D_ + b * T_;
    for (int t = tid; t < T_; t += 256) w[t] = __expf(sc[t] - mx) * inv;
}

// ---------------------------------------------------------------------------
// context[b,d] = sum_t w[b,t] * vh[b,t,d]  (fp16 values: half the traffic)
// grid (16, 32), 256 threads: 64 d-groups (8 halves) x 4-way t-interleave
// ---------------------------------------------------------------------------
__global__ void context_kernel(float* __restrict__ out) {
    int b  = blockIdx.y;
    int t0 = blockIdx.x * 128;
    int dg = (threadIdx.x & 63) * 8;
    int th = threadIdx.x >> 6;
    const float* w = out + B_ * D_ + b * T_ + t0;
    const uint4* v = (const uint4*)(g_vh + ((size_t)b * T_ + t0) * D_ + dg);
    float acc[8];
#pragma unroll
    for (int j = 0; j < 8; j++) acc[j] = 0.f;
#pragma unroll 4
    for (int t = th; t < 128; t += 4) {
        float wt = w[t];
        uint4 x = v[(size_t)t * (D_ / 8)];
        const __half2* h2 = (const __half2*)&x;
#pragma unroll
        for (int j = 0; j < 4; j++) {
            float2 f = __half22float2(h2[j]);
            acc[2*j]     = fmaf(wt, f.x, acc[2*j]);
            acc[2*j + 1] = fmaf(wt, f.y, acc[2*j + 1]);
        }
    }
    float* o = out + b * D_ + dg;
#pragma unroll
    for (int j = 0; j < 8; j++) atomicAdd(o + j, acc[j]);
}

// ---------------------------------------------------------------------------
extern "C" void kernel_launch(void* const* d_in, const int* in_sizes, int n_in,
                              void* d_out, int out_size) {
    const float* values = (const float*)d_in[0];
    const float* query  = (const float*)d_in[1];
    const float* W1w    = (const float*)d_in[2];
    const float* W1b    = (const float*)d_in[3];
    const float* W2w    = (const float*)d_in[4];
    const float* W2b    = (const float*)d_in[5];
    const float* Vw     = (const float*)d_in[6];
    // d_in[7] (V_b) unused: softmax is shift-invariant.
    float* out = (float*)d_out;

    cudaFuncSetAttribute(score_kernel, cudaFuncAttributeMaxDynamicSharedMemorySize,
                         SMEM_TOTAL);

    cudaMemsetAsync(out, 0, (size_t)B_ * D_ * sizeof(float), 0);
    convert_values_kernel<<<8192, 256>>>(values);
    convert_w1_kernel<<<dim3(16, 16), 256>>>(W1w);
    pq_kernel<<<B_, 512>>>(query, W2w, W1b, W2b);
    score_kernel<<<2048, 256, SMEM_TOTAL>>>(Vw);
    softmax_kernel<<<B_, 256>>>(out);
    context_kernel<<<dim3(16, B_), 256>>>(out);
}

// round 15
// speedup vs baseline: 1.3765x; 1.0243x over previous
#include <cuda_runtime.h>
#include <cuda_fp16.h>
#include <math.h>
#include <stdint.h>

#define B_ 32
#define T_ 2048
#define D_ 512
#define U_ 512
#define MT 65536            // B_*T_

// ---- score GEMM tiling ----
#define TILE_M 128
#define TILE_N 128
#define KC 64               // K elems per pipeline chunk (128B fp16 rows, SW128)
#define NCHUNK 8            // 512/64
#define A_H 0               // A plane: 128 rows x 128B = 16KB
#define B_H 16384           // B plane: 16KB
#define STAGE 32768
#define SMEM_TOTAL (2*STAGE + 1024)   // 66560 B -> 2 CTAs/SM

// ---- prelude partitioning ----
#define PRE_VAL 8192
#define PRE_W1  (PRE_VAL + 256)
#define PRE_PQ  (PRE_W1 + 64)
#define PRE_ZS  (PRE_PQ + 64)

// ---- scratch (device globals: allocation-free) ----
__device__ float g_score[MT];
__device__ float g_pq[B_ * U_];
__device__ __half g_vh[(size_t)MT * D_];
__device__ __half g_w1h[U_ * D_];   // [n][k] transposed, K-major

// ---------------------------------------------------------------------------
// PTX helpers — baseline (non-"a") features only
// ---------------------------------------------------------------------------
__device__ __forceinline__ uint32_t smem_u32(const void* p) {
    uint32_t a;
    asm("{ .reg .u64 t; cvta.to.shared.u64 t, %1; cvt.u32.u64 %0, t; }" : "=r"(a) : "l"(p));
    return a;
}
#define SWZ(o) ((o) ^ (((o) >> 3) & 0x70))   // SW128 for 128B rows

__device__ __forceinline__ void cp16(uint32_t dst, const void* src) {
    asm volatile("cp.async.cg.shared.global [%0], [%1], 16;" :: "r"(dst), "l"(src));
}
__device__ __forceinline__ void ldm4(uint32_t* r, uint32_t addr) {
    asm volatile("ldmatrix.sync.aligned.m8n8.x4.shared.b16 {%0,%1,%2,%3}, [%4];"
                 : "=r"(r[0]), "=r"(r[1]), "=r"(r[2]), "=r"(r[3]) : "r"(addr));
}
__device__ __forceinline__ void mma_f16(float* d, const uint32_t* a,
                                        uint32_t b0, uint32_t b1) {
    asm volatile(
        "mma.sync.aligned.m16n8k16.row.col.f32.f16.f16.f32 "
        "{%0,%1,%2,%3}, {%4,%5,%6,%7}, {%8,%9}, {%0,%1,%2,%3};"
        : "+f"(d[0]), "+f"(d[1]), "+f"(d[2]), "+f"(d[3])
        : "r"(a[0]), "r"(a[1]), "r"(a[2]), "r"(a[3]), "r"(b0), "r"(b1));
}

// ---------------------------------------------------------------------------
// Prelude: ALL independent prep work in one launch, partitioned by blockIdx.
//   [0, PRE_VAL)   values fp32 -> fp16
//   [PRE_VAL,W1)   W1 [K][N] -> transposed fp16 [N][K]
//   [PRE_W1,PQ)    proj_q + bias fold (2 blocks per batch)
//   [PRE_PQ,ZS)    zero g_score
// ---------------------------------------------------------------------------
__global__ void prelude_kernel(const float* __restrict__ values,
                               const float* __restrict__ query,
                               const float* __restrict__ W1,
                               const float* __restrict__ W2,
                               const float* __restrict__ W1b,
                               const float* __restrict__ W2b) {
    __shared__ float sh[32 * 33];      // shared by W1-transpose and pq branches
    const int blk = blockIdx.x;
    const int tid = threadIdx.x;

    if (blk < PRE_VAL) {
        const float4* v4 = (const float4*)values;
        __half2* vh2 = (__half2*)g_vh;
        size_t n4 = (size_t)MT * D_ / 4;
        for (size_t i = (size_t)blk * 256 + tid; i < n4;
             i += (size_t)PRE_VAL * 256) {
            float4 x = v4[i];
            __half2 h0, h1;
            h0.x = __float2half(x.x); h0.y = __float2half(x.y);
            h1.x = __float2half(x.z); h1.y = __float2half(x.w);
            vh2[2*i] = h0; vh2[2*i+1] = h1;
        }
    } else if (blk < PRE_W1) {
        int w = blk - PRE_VAL;             // 0..255
        int n0 = (w & 15) * 32, k0 = (w >> 4) * 32;
        int tx = tid & 31, ty = tid >> 5;  // ty 0..7
        float (*t)[33] = (float(*)[33])sh;
        for (int r = ty; r < 32; r += 8) t[r][tx] = W1[(k0 + r) * U_ + n0 + tx];
        __syncthreads();
        for (int r = ty; r < 32; r += 8)
            g_w1h[(size_t)(n0 + r) * D_ + k0 + tx] = __float2half(t[tx][r]);
    } else if (blk < PRE_PQ) {
        int w = blk - PRE_W1;              // 0..63
        int b = w >> 1;
        int u = (w & 1) * 256 + tid;
        sh[tid]       = query[b * D_ + tid];
        sh[256 + tid] = query[b * D_ + 256 + tid];
        __syncthreads();
        float acc = 0.f;
#pragma unroll 8
        for (int d = 0; d < D_; d++) acc = fmaf(sh[d], W2[d * U_ + u], acc);
        g_pq[b * U_ + u] = acc + W1b[u] + W2b[u];
    } else {
        int w = blk - PRE_PQ;              // 0..63
        float4 z = make_float4(0.f, 0.f, 0.f, 0.f);
        ((float4*)g_score)[w * 256 + tid] = z;
    }
}

// ---------------------------------------------------------------------------
// Score GEMM: single fp16 mma.sync, 2-stage cp.async pipeline,
// fused tanhf/Vw epilogue (EXACT R13 structure — proven 144.0us config).
// grid 2048 = 512 m-tiles x 4 n-slices; 256 threads (8 warps, 64x32 each)
// ---------------------------------------------------------------------------
extern __shared__ char smem_raw[];

__global__ __launch_bounds__(256, 2)
void score_kernel(const float* __restrict__ Vw) {
    const int tid  = threadIdx.x;
    const int lane = tid & 31;
    const int mtile = blockIdx.x >> 2;
    const int nq    = blockIdx.x & 3;
    const int row0  = mtile * TILE_M;
    const int b     = row0 >> 11;          // T_=2048
    const int n0    = nq * TILE_N;
    const int wid   = tid >> 5;
    const int m_w   = (wid >> 2) * 64;
    const int n_w   = (wid & 3) * 32;

    uint32_t sb = smem_u32(smem_raw);
    float* pqs = (float*)(smem_raw + 2 * STAGE);
    float* vws = pqs + 128;
    if (tid < 128) {
        pqs[tid] = g_pq[b * U_ + n0 + tid];
        vws[tid] = Vw[n0 + tid];
    }

    // ldmatrix per-lane address components (XOR swizzle folded per-lane)
    const int rowA = lane & 15;
    const int colA = (lane >> 4) * 16;                   // 16B chunk within k16 step
    const uint32_t axor = (rowA & 7) * 16;
    const int rowB = (lane & 7) + ((lane >> 3) & 1) * 8;
    const int colB = (lane >> 4) * 16;
    const uint32_t bxor = (rowB & 7) * 16;

    float acc[4][4][4];
#pragma unroll
    for (int i = 0; i < 4; i++)
#pragma unroll
        for (int j = 0; j < 4; j++)
#pragma unroll
            for (int r = 0; r < 4; r++) acc[i][j][r] = 0.f;

    const __half* Agh = g_vh  + (size_t)row0 * D_;
    const __half* Bgh = g_w1h + (size_t)n0   * D_;

    // loader: each plane 1024 granules (16B); 256 thr x 4 iters per plane
    const int lrow = tid >> 1;
    const int lch0 = (tid & 1) * 4;

#define LOAD_CHUNK(c, s)                                                     \
    do {                                                                     \
        uint32_t st = sb + (s) * STAGE;                                      \
        int k0 = (c) * KC;                                                   \
        _Pragma("unroll")                                                    \
        for (int i = 0; i < 4; i++) {                                        \
            int c16 = lch0 + i;                                              \
            uint32_t doff = SWZ(lrow * 128 + c16 * 16);                      \
            size_t soff = (size_t)lrow * D_ + k0 + c16 * 8;                  \
            cp16(st + A_H + doff, Agh + soff);                               \
            cp16(st + B_H + doff, Bgh + soff);                               \
        }                                                                    \
        asm volatile("cp.async.commit_group;" ::: "memory");                 \
    } while (0)

    LOAD_CHUNK(0, 0);

    // per-lane fragment bases (row part linear; col part XORed per k-step)
    const uint32_t aho = A_H + (m_w + rowA) * 128;
    const uint32_t bho = B_H + (n_w + rowB) * 128;

    for (int c = 0; c < NCHUNK; c++) {
        int s = c & 1;
        if (c + 1 < NCHUNK) {
            LOAD_CHUNK(c + 1, s ^ 1);
            asm volatile("cp.async.wait_group 1;" ::: "memory");
        } else {
            asm volatile("cp.async.wait_group 0;" ::: "memory");
        }
        __syncthreads();

        const uint32_t st = sb + s * STAGE;
#pragma unroll
        for (int k = 0; k < 4; k++) {                 // 4 x k16 per 64-chunk
            const uint32_t ka = (uint32_t)((k * 32 + colA) ^ axor);
            const uint32_t kb = (uint32_t)((k * 32 + colB) ^ bxor);

            uint32_t ah[4][4], bh[2][4];
#pragma unroll
            for (int i = 0; i < 4; i++)
                ldm4(ah[i], st + aho + i * 2048 + ka);
#pragma unroll
            for (int jj = 0; jj < 2; jj++)
                ldm4(bh[jj], st + bho + jj * 2048 + kb);
#pragma unroll
            for (int i = 0; i < 4; i++)
#pragma unroll
                for (int j = 0; j < 4; j++)
                    mma_f16(acc[i][j], ah[i],
                            bh[j >> 1][j & 1], bh[j >> 1][2 + (j & 1)]);
        }
        __syncthreads();
    }

    // Epilogue: tanhf(acc+pq)*Vw, reduce over n (shfl -> atomicAdd)
    float part[4][2];
#pragma unroll
    for (int i = 0; i < 4; i++) { part[i][0] = 0.f; part[i][1] = 0.f; }
#pragma unroll
    for (int i = 0; i < 4; i++)
#pragma unroll
        for (int j = 0; j < 4; j++)
#pragma unroll
            for (int r = 0; r < 4; r++) {
                int nl = n_w + j * 8 + 2 * (lane & 3) + (r & 1);
                float x = acc[i][j][r] + pqs[nl];
                part[i][r >> 1] += tanhf(x) * vws[nl];
            }
#pragma unroll
    for (int i = 0; i < 4; i++)
#pragma unroll
        for (int h = 0; h < 2; h++) {
            float v = part[i][h];
            v += __shfl_xor_sync(0xffffffffu, v, 1);
            v += __shfl_xor_sync(0xffffffffu, v, 2);
            if ((lane & 3) == 0)
                atomicAdd(&g_score[row0 + m_w + i * 16 + h * 8 + (lane >> 2)], v);
        }
}

// ---------------------------------------------------------------------------
// Softmax over T per batch; weights -> d_out[B*D ..)
// ---------------------------------------------------------------------------
__global__ void softmax_kernel(float* __restrict__ out) {
    __shared__ float sm[256];
    int b = blockIdx.x, tid = threadIdx.x;
    const float* sc = g_score + b * T_;
    float m = -1e30f;
    for (int t = tid; t < T_; t += 256) m = fmaxf(m, sc[t]);
    sm[tid] = m; __syncthreads();
    for (int s = 128; s > 0; s >>= 1) {
        if (tid < s) sm[tid] = fmaxf(sm[tid], sm[tid + s]);
        __syncthreads();
    }
    float mx = sm[0]; __syncthreads();
    float sum = 0.f;
    for (int t = tid; t < T_; t += 256) sum += __expf(sc[t] - mx);
    sm[tid] = sum; __syncthreads();
    for (int s = 128; s > 0; s >>= 1) {
        if (tid < s) sm[tid] += sm[tid + s];
        __syncthreads();
    }
    float inv = 1.f / sm[0];
    float* w = out + B_ * D_ + b * T_;
    for (int t = tid; t < T_; t += 256) w[t] = __expf(sc[t] - mx) * inv;
}

// ---------------------------------------------------------------------------
// context[b,d] = sum_t w[b,t] * vh[b,t,d]  (fp16 values: half the traffic)
// grid (16, 32), 256 threads: 64 d-groups (8 halves) x 4-way t-interleave
// ---------------------------------------------------------------------------
__global__ void context_kernel(float* __restrict__ out) {
    int b  = blockIdx.y;
    int t0 = blockIdx.x * 128;
    int dg = (threadIdx.x & 63) * 8;
    int th = threadIdx.x >> 6;
    const float* w = out + B_ * D_ + b * T_ + t0;
    const uint4* v = (const uint4*)(g_vh + ((size_t)b * T_ + t0) * D_ + dg);
    float acc[8];
#pragma unroll
    for (int j = 0; j < 8; j++) acc[j] = 0.f;
#pragma unroll 4
    for (int t = th; t < 128; t += 4) {
        float wt = w[t];
        uint4 x = v[(size_t)t * (D_ / 8)];
        const __half2* h2 = (const __half2*)&x;
#pragma unroll
        for (int j = 0; j < 4; j++) {
            float2 f = __half22float2(h2[j]);
            acc[2*j]     = fmaf(wt, f.x, acc[2*j]);
            acc[2*j + 1] = fmaf(wt, f.y, acc[2*j + 1]);
        }
    }
    float* o = out + b * D_ + dg;
#pragma unroll
    for (int j = 0; j < 8; j++) atomicAdd(o + j, acc[j]);
}

// ---------------------------------------------------------------------------
extern "C" void kernel_launch(void* const* d_in, const int* in_sizes, int n_in,
                              void* d_out, int out_size) {
    const float* values = (const float*)d_in[0];
    const float* query  = (const float*)d_in[1];
    const float* W1w    = (const float*)d_in[2];
    const float* W1b    = (const float*)d_in[3];
    const float* W2w    = (const float*)d_in[4];
    const float* W2b    = (const float*)d_in[5];
    const float* Vw     = (const float*)d_in[6];
    // d_in[7] (V_b) unused: softmax is shift-invariant.
    float* out = (float*)d_out;

    cudaFuncSetAttribute(score_kernel, cudaFuncAttributeMaxDynamicSharedMemorySize,
                         SMEM_TOTAL);

    cudaMemsetAsync(out, 0, (size_t)B_ * D_ * sizeof(float), 0);
    prelude_kernel<<<PRE_ZS, 256>>>(values, query, W1w, W2w, W1b, W2b);
    score_kernel<<<2048, 256, SMEM_TOTAL>>>(Vw);
    softmax_kernel<<<B_, 256>>>(out);
    context_kernel<<<dim3(16, B_), 256>>>(out);
}

// round 16
// speedup vs baseline: 1.4661x; 1.0651x over previous
#include <cuda_runtime.h>
#include <cuda_fp16.h>
#include <math.h>
#include <stdint.h>

#define B_ 32
#define T_ 2048
#define D_ 512
#define U_ 512
#define MT 65536            // B_*T_

// ---- score GEMM tiling ----
#define TILE_M 128
#define TILE_N 128
#define KC 64               // K elems per pipeline chunk (128B fp16 rows, SW128)
#define NCHUNK 8            // 512/64
#define A_H 0               // A plane: 128 rows x 128B = 16KB
#define B_H 16384           // B plane: 16KB
#define STAGE 32768
#define SMEM_TOTAL (2*STAGE + 1024)   // 66560 B -> 2 CTAs/SM

// ---- prelude partitioning ----
#define PRE_VAL 8192
#define PRE_W1  (PRE_VAL + 256)
#define PRE_PQ  (PRE_W1 + 64)
#define PRE_ZS  (PRE_PQ + 64)

// ---- scratch (device globals: allocation-free) ----
__device__ float g_score[MT];
__device__ float g_pq[B_ * U_];
__device__ __half g_vh[(size_t)MT * D_];
__device__ __half g_w1h[U_ * D_];   // [n][k] transposed, K-major

// ---------------------------------------------------------------------------
// PTX helpers — baseline (non-"a") features only
// ---------------------------------------------------------------------------
__device__ __forceinline__ uint32_t smem_u32(const void* p) {
    uint32_t a;
    asm("{ .reg .u64 t; cvta.to.shared.u64 t, %1; cvt.u32.u64 %0, t; }" : "=r"(a) : "l"(p));
    return a;
}
#define SWZ(o) ((o) ^ (((o) >> 3) & 0x70))   // SW128 for 128B rows

__device__ __forceinline__ void cp16(uint32_t dst, const void* src) {
    asm volatile("cp.async.cg.shared.global [%0], [%1], 16;" :: "r"(dst), "l"(src));
}
__device__ __forceinline__ void ldm4(uint32_t* r, uint32_t addr) {
    asm volatile("ldmatrix.sync.aligned.m8n8.x4.shared.b16 {%0,%1,%2,%3}, [%4];"
                 : "=r"(r[0]), "=r"(r[1]), "=r"(r[2]), "=r"(r[3]) : "r"(addr));
}
__device__ __forceinline__ void mma_f16(float* d, const uint32_t* a,
                                        uint32_t b0, uint32_t b1) {
    asm volatile(
        "mma.sync.aligned.m16n8k16.row.col.f32.f16.f16.f32 "
        "{%0,%1,%2,%3}, {%4,%5,%6,%7}, {%8,%9}, {%0,%1,%2,%3};"
        : "+f"(d[0]), "+f"(d[1]), "+f"(d[2]), "+f"(d[3])
        : "r"(a[0]), "r"(a[1]), "r"(a[2]), "r"(a[3]), "r"(b0), "r"(b1));
}

// ---------------------------------------------------------------------------
// Prelude: ALL independent prep work in one launch, partitioned by blockIdx.
//   [0, PRE_VAL)   values fp32 -> fp16
//   [PRE_VAL,W1)   W1 [K][N] -> transposed fp16 [N][K]
//   [PRE_W1,PQ)    proj_q + bias fold (2 blocks per batch)
//   [PRE_PQ,ZS)    zero g_score + zero out[0..B*D) (context atomic target)
// ---------------------------------------------------------------------------
__global__ void prelude_kernel(const float* __restrict__ values,
                               const float* __restrict__ query,
                               const float* __restrict__ W1,
                               const float* __restrict__ W2,
                               const float* __restrict__ W1b,
                               const float* __restrict__ W2b,
                               float* __restrict__ out) {
    __shared__ float sh[32 * 33];      // shared by W1-transpose and pq branches
    const int blk = blockIdx.x;
    const int tid = threadIdx.x;

    if (blk < PRE_VAL) {
        const float4* v4 = (const float4*)values;
        __half2* vh2 = (__half2*)g_vh;
        size_t n4 = (size_t)MT * D_ / 4;
        for (size_t i = (size_t)blk * 256 + tid; i < n4;
             i += (size_t)PRE_VAL * 256) {
            float4 x = v4[i];
            __half2 h0, h1;
            h0.x = __float2half(x.x); h0.y = __float2half(x.y);
            h1.x = __float2half(x.z); h1.y = __float2half(x.w);
            vh2[2*i] = h0; vh2[2*i+1] = h1;
        }
    } else if (blk < PRE_W1) {
        int w = blk - PRE_VAL;             // 0..255
        int n0 = (w & 15) * 32, k0 = (w >> 4) * 32;
        int tx = tid & 31, ty = tid >> 5;  // ty 0..7
        float (*t)[33] = (float(*)[33])sh;
        for (int r = ty; r < 32; r += 8) t[r][tx] = W1[(k0 + r) * U_ + n0 + tx];
        __syncthreads();
        for (int r = ty; r < 32; r += 8)
            g_w1h[(size_t)(n0 + r) * D_ + k0 + tx] = __float2half(t[tx][r]);
    } else if (blk < PRE_PQ) {
        int w = blk - PRE_W1;              // 0..63
        int b = w >> 1;
        int u = (w & 1) * 256 + tid;
        sh[tid]       = query[b * D_ + tid];
        sh[256 + tid] = query[b * D_ + 256 + tid];
        __syncthreads();
        float acc = 0.f;
#pragma unroll 8
        for (int d = 0; d < D_; d++) acc = fmaf(sh[d], W2[d * U_ + u], acc);
        g_pq[b * U_ + u] = acc + W1b[u] + W2b[u];
    } else {
        int w = blk - PRE_PQ;              // 0..63
        float4 z = make_float4(0.f, 0.f, 0.f, 0.f);
        ((float4*)g_score)[w * 256 + tid] = z;
        if (w < 16)                        // out context region: 16K floats
            ((float4*)out)[w * 256 + tid] = z;
    }
}

// ---------------------------------------------------------------------------
// Score GEMM: single fp16 mma.sync, 2-stage cp.async pipeline,
// fused tanhf/Vw epilogue (EXACT R13 structure — proven 144.0us config).
// grid 2048 = 512 m-tiles x 4 n-slices; 256 threads (8 warps, 64x32 each)
// ---------------------------------------------------------------------------
extern __shared__ char smem_raw[];

__global__ __launch_bounds__(256, 2)
void score_kernel(const float* __restrict__ Vw) {
    const int tid  = threadIdx.x;
    const int lane = tid & 31;
    const int mtile = blockIdx.x >> 2;
    const int nq    = blockIdx.x & 3;
    const int row0  = mtile * TILE_M;
    const int b     = row0 >> 11;          // T_=2048
    const int n0    = nq * TILE_N;
    const int wid   = tid >> 5;
    const int m_w   = (wid >> 2) * 64;
    const int n_w   = (wid & 3) * 32;

    uint32_t sb = smem_u32(smem_raw);
    float* pqs = (float*)(smem_raw + 2 * STAGE);
    float* vws = pqs + 128;
    if (tid < 128) {
        pqs[tid] = g_pq[b * U_ + n0 + tid];
        vws[tid] = Vw[n0 + tid];
    }

    // ldmatrix per-lane address components (XOR swizzle folded per-lane)
    const int rowA = lane & 15;
    const int colA = (lane >> 4) * 16;                   // 16B chunk within k16 step
    const uint32_t axor = (rowA & 7) * 16;
    const int rowB = (lane & 7) + ((lane >> 3) & 1) * 8;
    const int colB = (lane >> 4) * 16;
    const uint32_t bxor = (rowB & 7) * 16;

    float acc[4][4][4];
#pragma unroll
    for (int i = 0; i < 4; i++)
#pragma unroll
        for (int j = 0; j < 4; j++)
#pragma unroll
            for (int r = 0; r < 4; r++) acc[i][j][r] = 0.f;

    const __half* Agh = g_vh  + (size_t)row0 * D_;
    const __half* Bgh = g_w1h + (size_t)n0   * D_;

    // loader: each plane 1024 granules (16B); 256 thr x 4 iters per plane
    const int lrow = tid >> 1;
    const int lch0 = (tid & 1) * 4;

#define LOAD_CHUNK(c, s)                                                     \
    do {                                                                     \
        uint32_t st = sb + (s) * STAGE;                                      \
        int k0 = (c) * KC;                                                   \
        _Pragma("unroll")                                                    \
        for (int i = 0; i < 4; i++) {                                        \
            int c16 = lch0 + i;                                              \
            uint32_t doff = SWZ(lrow * 128 + c16 * 16);                      \
            size_t soff = (size_t)lrow * D_ + k0 + c16 * 8;                  \
            cp16(st + A_H + doff, Agh + soff);                               \
            cp16(st + B_H + doff, Bgh + soff);                               \
        }                                                                    \
        asm volatile("cp.async.commit_group;" ::: "memory");                 \
    } while (0)

    LOAD_CHUNK(0, 0);

    // per-lane fragment bases (row part linear; col part XORed per k-step)
    const uint32_t aho = A_H + (m_w + rowA) * 128;
    const uint32_t bho = B_H + (n_w + rowB) * 128;

    for (int c = 0; c < NCHUNK; c++) {
        int s = c & 1;
        if (c + 1 < NCHUNK) {
            LOAD_CHUNK(c + 1, s ^ 1);
            asm volatile("cp.async.wait_group 1;" ::: "memory");
        } else {
            asm volatile("cp.async.wait_group 0;" ::: "memory");
        }
        __syncthreads();

        const uint32_t st = sb + s * STAGE;
#pragma unroll
        for (int k = 0; k < 4; k++) {                 // 4 x k16 per 64-chunk
            const uint32_t ka = (uint32_t)((k * 32 + colA) ^ axor);
            const uint32_t kb = (uint32_t)((k * 32 + colB) ^ bxor);

            uint32_t ah[4][4], bh[2][4];
#pragma unroll
            for (int i = 0; i < 4; i++)
                ldm4(ah[i], st + aho + i * 2048 + ka);
#pragma unroll
            for (int jj = 0; jj < 2; jj++)
                ldm4(bh[jj], st + bho + jj * 2048 + kb);
#pragma unroll
            for (int i = 0; i < 4; i++)
#pragma unroll
                for (int j = 0; j < 4; j++)
                    mma_f16(acc[i][j], ah[i],
                            bh[j >> 1][j & 1], bh[j >> 1][2 + (j & 1)]);
        }
        __syncthreads();
    }

    // Epilogue: tanhf(acc+pq)*Vw, reduce over n (shfl -> atomicAdd)
    float part[4][2];
#pragma unroll
    for (int i = 0; i < 4; i++) { part[i][0] = 0.f; part[i][1] = 0.f; }
#pragma unroll
    for (int i = 0; i < 4; i++)
#pragma unroll
        for (int j = 0; j < 4; j++)
#pragma unroll
            for (int r = 0; r < 4; r++) {
                int nl = n_w + j * 8 + 2 * (lane & 3) + (r & 1);
                float x = acc[i][j][r] + pqs[nl];
                part[i][r >> 1] += tanhf(x) * vws[nl];
            }
#pragma unroll
    for (int i = 0; i < 4; i++)
#pragma unroll
        for (int h = 0; h < 2; h++) {
            float v = part[i][h];
            v += __shfl_xor_sync(0xffffffffu, v, 1);
            v += __shfl_xor_sync(0xffffffffu, v, 2);
            if ((lane & 3) == 0)
                atomicAdd(&g_score[row0 + m_w + i * 16 + h * 8 + (lane >> 2)], v);
        }
}

// ---------------------------------------------------------------------------
// Softmax over T per batch; weights -> d_out[B*D ..)
// ---------------------------------------------------------------------------
__global__ void softmax_kernel(float* __restrict__ out) {
    __shared__ float sm[256];
    int b = blockIdx.x, tid = threadIdx.x;
    const float* sc = g_score + b * T_;
    float m = -1e30f;
    for (int t = tid; t < T_; t += 256) m = fmaxf(m, sc[t]);
    sm[tid] = m; __syncthreads();
    for (int s = 128; s > 0; s >>= 1) {
        if (tid < s) sm[tid] = fmaxf(sm[tid], sm[tid + s]);
        __syncthreads();
    }
    float mx = sm[0]; __syncthreads();
    float sum = 0.f;
    for (int t = tid; t < T_; t += 256) sum += __expf(sc[t] - mx);
    sm[tid] = sum; __syncthreads();
    for (int s = 128; s > 0; s >>= 1) {
        if (tid < s) sm[tid] += sm[tid + s];
        __syncthreads();
    }
    float inv = 1.f / sm[0];
    float* w = out + B_ * D_ + b * T_;
    for (int t = tid; t < T_; t += 256) w[t] = __expf(sc[t] - mx) * inv;
}

// ---------------------------------------------------------------------------
// context[b,d] = sum_t w[b,t] * vh[b,t,d]  (fp16 values)
// grid (32, 32) = 1024 blocks, 256 thr: t-chunk 64, 64 d-groups x 4 t-lanes,
// fully-unrolled 16 independent loads (MLP~16), smem-staged reduction,
// 2 atomics/thread (spread addresses).
// ---------------------------------------------------------------------------
__global__ void context_kernel(float* __restrict__ out) {
    __shared__ float red[4][512];
    int b  = blockIdx.y;
    int t0 = blockIdx.x * 64;
    int dg = (threadIdx.x & 63) * 8;
    int th = threadIdx.x >> 6;          // 0..3
    const float* w = out + B_ * D_ + b * T_ + t0;
    const uint4* v = (const uint4*)(g_vh + ((size_t)b * T_ + t0) * D_ + dg);
    float acc[8];
#pragma unroll
    for (int j = 0; j < 8; j++) acc[j] = 0.f;
#pragma unroll
    for (int t = th; t < 64; t += 4) {          // 16 fully-unrolled iterations
        float wt = w[t];
        uint4 x = v[(size_t)t * (D_ / 8)];
        const __half2* h2 = (const __half2*)&x;
#pragma unroll
        for (int j = 0; j < 4; j++) {
            float2 f = __half22float2(h2[j]);
            acc[2*j]     = fmaf(wt, f.x, acc[2*j]);
            acc[2*j + 1] = fmaf(wt, f.y, acc[2*j + 1]);
        }
    }
#pragma unroll
    for (int j = 0; j < 8; j++) red[th][dg + j] = acc[j];
    __syncthreads();
    int d0 = threadIdx.x * 2;
    float s0 = red[0][d0]     + red[1][d0]     + red[2][d0]     + red[3][d0];
    float s1 = red[0][d0 + 1] + red[1][d0 + 1] + red[2][d0 + 1] + red[3][d0 + 1];
    atomicAdd(&out[b * D_ + d0],     s0);
    atomicAdd(&out[b * D_ + d0 + 1], s1);
}

// ---------------------------------------------------------------------------
extern "C" void kernel_launch(void* const* d_in, const int* in_sizes, int n_in,
                              void* d_out, int out_size) {
    const float* values = (const float*)d_in[0];
    const float* query  = (const float*)d_in[1];
    const float* W1w    = (const float*)d_in[2];
    const float* W1b    = (const float*)d_in[3];
    const float* W2w    = (const float*)d_in[4];
    const float* W2b    = (const float*)d_in[5];
    const float* Vw     = (const float*)d_in[6];
    // d_in[7] (V_b) unused: softmax is shift-invariant.
    float* out = (float*)d_out;

    cudaFuncSetAttribute(score_kernel, cudaFuncAttributeMaxDynamicSharedMemorySize,
                         SMEM_TOTAL);

    prelude_kernel<<<PRE_ZS, 256>>>(values, query, W1w, W2w, W1b, W2b, out);
    score_kernel<<<2048, 256, SMEM_TOTAL>>>(Vw);
    softmax_kernel<<<B_, 256>>>(out);
    context_kernel<<<dim3(32, B_), 256>>>(out);
}

// round 17
// speedup vs baseline: 1.5077x; 1.0284x over previous
#include <cuda_runtime.h>
#include <cuda_fp16.h>
#include <math.h>
#include <stdint.h>

#define B_ 32
#define T_ 2048
#define D_ 512
#define U_ 512
#define MT 65536            // B_*T_

// ---- score GEMM tiling ----
#define TILE_M 128
#define TILE_N 128
#define KC 64               // K elems per pipeline chunk (128B fp16 rows, SW128)
#define NCHUNK 8            // 512/64
#define A_H 0               // A plane: 128 rows x 128B = 16KB
#define B_H 16384           // B plane: 16KB
#define STAGE 32768
#define SMEM_TOTAL (2*STAGE + 1024)   // 66560 B -> 2 CTAs/SM

// ---- prelude partitioning ----
#define PRE_VAL 8192
#define PRE_W1  (PRE_VAL + 256)
#define PRE_PQ  (PRE_W1 + 64)
#define PRE_ZS  (PRE_PQ + 64)

// ---- scratch (device globals: allocation-free) ----
__device__ float g_score[MT];
__device__ float g_pq[B_ * U_];
__device__ float g_inv[B_];
__device__ __half g_vh[(size_t)MT * D_];
__device__ __half g_w1h[U_ * D_];   // [n][k] transposed, K-major

// ---------------------------------------------------------------------------
// PTX helpers — baseline (non-"a") features only
// ---------------------------------------------------------------------------
__device__ __forceinline__ uint32_t smem_u32(const void* p) {
    uint32_t a;
    asm("{ .reg .u64 t; cvta.to.shared.u64 t, %1; cvt.u32.u64 %0, t; }" : "=r"(a) : "l"(p));
    return a;
}
#define SWZ(o) ((o) ^ (((o) >> 3) & 0x70))   // SW128 for 128B rows

__device__ __forceinline__ void cp16(uint32_t dst, const void* src) {
    asm volatile("cp.async.cg.shared.global [%0], [%1], 16;" :: "r"(dst), "l"(src));
}
__device__ __forceinline__ void ldm4(uint32_t* r, uint32_t addr) {
    asm volatile("ldmatrix.sync.aligned.m8n8.x4.shared.b16 {%0,%1,%2,%3}, [%4];"
                 : "=r"(r[0]), "=r"(r[1]), "=r"(r[2]), "=r"(r[3]) : "r"(addr));
}
__device__ __forceinline__ void mma_f16(float* d, const uint32_t* a,
                                        uint32_t b0, uint32_t b1) {
    asm volatile(
        "mma.sync.aligned.m16n8k16.row.col.f32.f16.f16.f32 "
        "{%0,%1,%2,%3}, {%4,%5,%6,%7}, {%8,%9}, {%0,%1,%2,%3};"
        : "+f"(d[0]), "+f"(d[1]), "+f"(d[2]), "+f"(d[3])
        : "r"(a[0]), "r"(a[1]), "r"(a[2]), "r"(a[3]), "r"(b0), "r"(b1));
}

// ---------------------------------------------------------------------------
// Prelude: ALL independent prep work in one launch, partitioned by blockIdx.
//   [0, PRE_VAL)   values fp32 -> fp16 (vectorized: 2x16B loads, 1x16B store)
//   [PRE_VAL,W1)   W1 [K][N] -> transposed fp16 [N][K]
//   [PRE_W1,PQ)    proj_q + bias fold (2 blocks per batch)
//   [PRE_PQ,ZS)    zero g_score + zero out[0..B*D) (context atomic target)
// ---------------------------------------------------------------------------
__global__ void prelude_kernel(const float* __restrict__ values,
                               const float* __restrict__ query,
                               const float* __restrict__ W1,
                               const float* __restrict__ W2,
                               const float* __restrict__ W1b,
                               const float* __restrict__ W2b,
                               float* __restrict__ out) {
    __shared__ float sh[32 * 33];      // shared by W1-transpose and pq branches
    const int blk = blockIdx.x;
    const int tid = threadIdx.x;

    if (blk < PRE_VAL) {
        const float4* v4 = (const float4*)values;
        uint4* vh4 = (uint4*)g_vh;
        size_t n8 = (size_t)MT * D_ / 8;
        for (size_t i = (size_t)blk * 256 + tid; i < n8;
             i += (size_t)PRE_VAL * 256) {
            float4 x = v4[2 * i];
            float4 y = v4[2 * i + 1];
            union { uint4 u; __half2 h[4]; } o;
            o.h[0] = __floats2half2_rn(x.x, x.y);
            o.h[1] = __floats2half2_rn(x.z, x.w);
            o.h[2] = __floats2half2_rn(y.x, y.y);
            o.h[3] = __floats2half2_rn(y.z, y.w);
            vh4[i] = o.u;
        }
    } else if (blk < PRE_W1) {
        int w = blk - PRE_VAL;             // 0..255
        int n0 = (w & 15) * 32, k0 = (w >> 4) * 32;
        int tx = tid & 31, ty = tid >> 5;  // ty 0..7
        float (*t)[33] = (float(*)[33])sh;
        for (int r = ty; r < 32; r += 8) t[r][tx] = W1[(k0 + r) * U_ + n0 + tx];
        __syncthreads();
        for (int r = ty; r < 32; r += 8)
            g_w1h[(size_t)(n0 + r) * D_ + k0 + tx] = __float2half(t[tx][r]);
    } else if (blk < PRE_PQ) {
        int w = blk - PRE_W1;              // 0..63
        int b = w >> 1;
        int u = (w & 1) * 256 + tid;
        sh[tid]       = query[b * D_ + tid];
        sh[256 + tid] = query[b * D_ + 256 + tid];
        __syncthreads();
        float acc = 0.f;
#pragma unroll 8
        for (int d = 0; d < D_; d++) acc = fmaf(sh[d], W2[d * U_ + u], acc);
        g_pq[b * U_ + u] = acc + W1b[u] + W2b[u];
    } else {
        int w = blk - PRE_PQ;              // 0..63
        float4 z = make_float4(0.f, 0.f, 0.f, 0.f);
        ((float4*)g_score)[w * 256 + tid] = z;
        if (w < 16)                        // out context region: 16K floats
            ((float4*)out)[w * 256 + tid] = z;
    }
}

// ---------------------------------------------------------------------------
// Score GEMM: single fp16 mma.sync, 2-stage cp.async pipeline,
// fused tanhf/Vw epilogue (EXACT R13 structure — proven 144.0us config).
// grid 2048 = 512 m-tiles x 4 n-slices; 256 threads (8 warps, 64x32 each)
// ---------------------------------------------------------------------------
extern __shared__ char smem_raw[];

__global__ __launch_bounds__(256, 2)
void score_kernel(const float* __restrict__ Vw) {
    const int tid  = threadIdx.x;
    const int lane = tid & 31;
    const int mtile = blockIdx.x >> 2;
    const int nq    = blockIdx.x & 3;
    const int row0  = mtile * TILE_M;
    const int b     = row0 >> 11;          // T_=2048
    const int n0    = nq * TILE_N;
    const int wid   = tid >> 5;
    const int m_w   = (wid >> 2) * 64;
    const int n_w   = (wid & 3) * 32;

    uint32_t sb = smem_u32(smem_raw);
    float* pqs = (float*)(smem_raw + 2 * STAGE);
    float* vws = pqs + 128;
    if (tid < 128) {
        pqs[tid] = g_pq[b * U_ + n0 + tid];
        vws[tid] = Vw[n0 + tid];
    }

    // ldmatrix per-lane address components (XOR swizzle folded per-lane)
    const int rowA = lane & 15;
    const int colA = (lane >> 4) * 16;                   // 16B chunk within k16 step
    const uint32_t axor = (rowA & 7) * 16;
    const int rowB = (lane & 7) + ((lane >> 3) & 1) * 8;
    const int colB = (lane >> 4) * 16;
    const uint32_t bxor = (rowB & 7) * 16;

    float acc[4][4][4];
#pragma unroll
    for (int i = 0; i < 4; i++)
#pragma unroll
        for (int j = 0; j < 4; j++)
#pragma unroll
            for (int r = 0; r < 4; r++) acc[i][j][r] = 0.f;

    const __half* Agh = g_vh  + (size_t)row0 * D_;
    const __half* Bgh = g_w1h + (size_t)n0   * D_;

    // loader: each plane 1024 granules (16B); 256 thr x 4 iters per plane
    const int lrow = tid >> 1;
    const int lch0 = (tid & 1) * 4;

#define LOAD_CHUNK(c, s)                                                     \
    do {                                                                     \
        uint32_t st = sb + (s) * STAGE;                                      \
        int k0 = (c) * KC;                                                   \
        _Pragma("unroll")                                                    \
        for (int i = 0; i < 4; i++) {                                        \
            int c16 = lch0 + i;                                              \
            uint32_t doff = SWZ(lrow * 128 + c16 * 16);                      \
            size_t soff = (size_t)lrow * D_ + k0 + c16 * 8;                  \
            cp16(st + A_H + doff, Agh + soff);                               \
            cp16(st + B_H + doff, Bgh + soff);                               \
        }                                                                    \
        asm volatile("cp.async.commit_group;" ::: "memory");                 \
    } while (0)

    LOAD_CHUNK(0, 0);

    // per-lane fragment bases (row part linear; col part XORed per k-step)
    const uint32_t aho = A_H + (m_w + rowA) * 128;
    const uint32_t bho = B_H + (n_w + rowB) * 128;

    for (int c = 0; c < NCHUNK; c++) {
        int s = c & 1;
        if (c + 1 < NCHUNK) {
            LOAD_CHUNK(c + 1, s ^ 1);
            asm volatile("cp.async.wait_group 1;" ::: "memory");
        } else {
            asm volatile("cp.async.wait_group 0;" ::: "memory");
        }
        __syncthreads();

        const uint32_t st = sb + s * STAGE;
#pragma unroll
        for (int k = 0; k < 4; k++) {                 // 4 x k16 per 64-chunk
            const uint32_t ka = (uint32_t)((k * 32 + colA) ^ axor);
            const uint32_t kb = (uint32_t)((k * 32 + colB) ^ bxor);

            uint32_t ah[4][4], bh[2][4];
#pragma unroll
            for (int i = 0; i < 4; i++)
                ldm4(ah[i], st + aho + i * 2048 + ka);
#pragma unroll
            for (int jj = 0; jj < 2; jj++)
                ldm4(bh[jj], st + bho + jj * 2048 + kb);
#pragma unroll
            for (int i = 0; i < 4; i++)
#pragma unroll
                for (int j = 0; j < 4; j++)
                    mma_f16(acc[i][j], ah[i],
                            bh[j >> 1][j & 1], bh[j >> 1][2 + (j & 1)]);
        }
        __syncthreads();
    }

    // Epilogue: tanhf(acc+pq)*Vw, reduce over n (shfl -> atomicAdd)
    float part[4][2];
#pragma unroll
    for (int i = 0; i < 4; i++) { part[i][0] = 0.f; part[i][1] = 0.f; }
#pragma unroll
    for (int i = 0; i < 4; i++)
#pragma unroll
        for (int j = 0; j < 4; j++)
#pragma unroll
            for (int r = 0; r < 4; r++) {
                int nl = n_w + j * 8 + 2 * (lane & 3) + (r & 1);
                float x = acc[i][j][r] + pqs[nl];
                part[i][r >> 1] += tanhf(x) * vws[nl];
            }
#pragma unroll
    for (int i = 0; i < 4; i++)
#pragma unroll
        for (int h = 0; h < 2; h++) {
            float v = part[i][h];
            v += __shfl_xor_sync(0xffffffffu, v, 1);
            v += __shfl_xor_sync(0xffffffffu, v, 2);
            if ((lane & 3) == 0)
                atomicAdd(&g_score[row0 + m_w + i * 16 + h * 8 + (lane >> 2)], v);
        }
}

// ---------------------------------------------------------------------------
// Sum of exp over T per batch -> g_inv[b] = 1/sum.
// No max subtraction: |score| <= ||Vw||_1 ~= 20, exp is safe in fp32.
// ---------------------------------------------------------------------------
__global__ void sumexp_kernel() {
    __shared__ float sm[256];
    int b = blockIdx.x, tid = threadIdx.x;
    const float* sc = g_score + b * T_;
    float s = 0.f;
    for (int t = tid; t < T_; t += 256) s += __expf(sc[t]);
    sm[tid] = s; __syncthreads();
    for (int r = 128; r > 0; r >>= 1) {
        if (tid < r) sm[tid] += sm[tid + r];
        __syncthreads();
    }
    if (tid == 0) g_inv[b] = 1.f / sm[0];
}

// ---------------------------------------------------------------------------
// context[b,d] = sum_t w[b,t] * vh[b,t,d]; also computes and writes the
// normalized weights w = exp(score)*inv (each (b,t) owned by exactly one block)
// grid (32, 32) = 1024 blocks, 256 thr: t-chunk 64, smem-staged reduction.
// ---------------------------------------------------------------------------
__global__ void context_kernel(float* __restrict__ out) {
    __shared__ float red[4][512];
    __shared__ float wsh[64];
    int b  = blockIdx.y;
    int t0 = blockIdx.x * 64;
    int dg = (threadIdx.x & 63) * 8;
    int th = threadIdx.x >> 6;          // 0..3
    if (threadIdx.x < 64) {
        float e = __expf(g_score[b * T_ + t0 + threadIdx.x]) * g_inv[b];
        wsh[threadIdx.x] = e;
        out[B_ * D_ + b * T_ + t0 + threadIdx.x] = e;
    }
    __syncthreads();
    const uint4* v = (const uint4*)(g_vh + ((size_t)b * T_ + t0) * D_ + dg);
    float acc[8];
#pragma unroll
    for (int j = 0; j < 8; j++) acc[j] = 0.f;
#pragma unroll
    for (int t = th; t < 64; t += 4) {          // 16 fully-unrolled iterations
        float wt = wsh[t];
        uint4 x = v[(size_t)t * (D_ / 8)];
        const __half2* h2 = (const __half2*)&x;
#pragma unroll
        for (int j = 0; j < 4; j++) {
            float2 f = __half22float2(h2[j]);
            acc[2*j]     = fmaf(wt, f.x, acc[2*j]);
            acc[2*j + 1] = fmaf(wt, f.y, acc[2*j + 1]);
        }
    }
#pragma unroll
    for (int j = 0; j < 8; j++) red[th][dg + j] = acc[j];
    __syncthreads();
    int d0 = threadIdx.x * 2;
    float s0 = red[0][d0]     + red[1][d0]     + red[2][d0]     + red[3][d0];
    float s1 = red[0][d0 + 1] + red[1][d0 + 1] + red[2][d0 + 1] + red[3][d0 + 1];
    atomicAdd(&out[b * D_ + d0],     s0);
    atomicAdd(&out[b * D_ + d0 + 1], s1);
}

// ---------------------------------------------------------------------------
extern "C" void kernel_launch(void* const* d_in, const int* in_sizes, int n_in,
                              void* d_out, int out_size) {
    const float* values = (const float*)d_in[0];
    const float* query  = (const float*)d_in[1];
    const float* W1w    = (const float*)d_in[2];
    const float* W1b    = (const float*)d_in[3];
    const float* W2w    = (const float*)d_in[4];
    const float* W2b    = (const float*)d_in[5];
    const float* Vw     = (const float*)d_in[6];
    // d_in[7] (V_b) unused: softmax is shift-invariant.
    float* out = (float*)d_out;

    cudaFuncSetAttribute(score_kernel, cudaFuncAttributeMaxDynamicSharedMemorySize,
                         SMEM_TOTAL);

    prelude_kernel<<<PRE_ZS, 256>>>(values, query, W1w, W2w, W1b, W2b, out);
    score_kernel<<<2048, 256, SMEM_TOTAL>>>(Vw);
    sumexp_kernel<<<B_, 256>>>();
    context_kernel<<<dim3(32, B_), 256>>>(out);
}